// round 8
// baseline (speedup 1.0000x reference)
#include <cuda_runtime.h>
#include <cuda_fp16.h>
#include <math.h>
#include <stdint.h>

#define Hdim 2048
#define Idim 4096
#define Edim 8
#define Tdim 2048
#define TK   4096   // T * K slots (always exact: every token picks 2 experts)

// ---------------- scratch (static device arrays; no allocations) ----------------
__device__ __half d_tn[(size_t)Tdim * Hdim];  // normalized tokens (fp16)
__device__ float  d_g[(size_t)TK * Idim];     // gate proj (fp32)
__device__ __half d_h[(size_t)TK * Idim];     // silu(g)*u (fp16)
__device__ int    d_rows[TK];
__device__ float  d_wgt[TK];
__device__ int    d_topi[Tdim * 2];
__device__ float  d_topw[Tdim * 2];
__device__ int    d_counts[Edim];
__device__ int    d_cursor[Edim];
__device__ int    d_offsets[Edim + 1];

// ---------------- helpers ----------------
__device__ __forceinline__ float warpsum(float v) {
#pragma unroll
    for (int o = 16; o > 0; o >>= 1) v += __shfl_down_sync(0xFFFFFFFFu, v, o);
    return v;
}
__device__ __forceinline__ uint32_t smem_u32(const void* p) {
    uint32_t a;
    asm("{ .reg .u64 t; cvta.to.shared.u64 t, %1; cvt.u32.u64 %0, t; }" : "=r"(a) : "l"(p));
    return a;
}
__device__ __forceinline__ void cp16(uint32_t dst, const void* src) {
    asm volatile("cp.async.cg.shared.global [%0], [%1], 16;" :: "r"(dst), "l"(src) : "memory");
}
__device__ __forceinline__ unsigned pack2h(float lo, float hi) {
    __half2 h = __floats2half2_rn(lo, hi);   // .x (lo) in low 16 bits
    return *reinterpret_cast<unsigned*>(&h);
}
__device__ __forceinline__ void mma_f16(float c[4], const unsigned a[4],
                                        unsigned b0, unsigned b1) {
    asm volatile(
        "mma.sync.aligned.m16n8k16.row.col.f32.f16.f16.f32 "
        "{%0,%1,%2,%3}, {%4,%5,%6,%7}, {%8,%9}, {%0,%1,%2,%3};"
        : "+f"(c[0]), "+f"(c[1]), "+f"(c[2]), "+f"(c[3])
        : "r"(a[0]), "r"(a[1]), "r"(a[2]), "r"(a[3]), "r"(b0), "r"(b1));
}
__device__ __forceinline__ void ldsm4(unsigned r[4], uint32_t addr) {
    asm volatile("ldmatrix.sync.aligned.m8n8.x4.shared.b16 {%0,%1,%2,%3}, [%4];"
                 : "=r"(r[0]), "=r"(r[1]), "=r"(r[2]), "=r"(r[3]) : "r"(addr));
}

// ---------------- init ----------------
__global__ void init_kernel(float* __restrict__ out) {
    size_t n = (size_t)Tdim * Hdim;
    for (size_t i = (size_t)blockIdx.x * blockDim.x + threadIdx.x; i < n;
         i += (size_t)gridDim.x * blockDim.x)
        out[i] = 0.0f;
    if (blockIdx.x == 0 && threadIdx.x < Edim) {
        d_counts[threadIdx.x] = 0;
        d_cursor[threadIdx.x] = 0;
    }
}

// ---------------- RMSNorm + router + top-2 ----------------
__global__ __launch_bounds__(256) void routing_kernel(const float* __restrict__ x,
                                                      const float* __restrict__ nw,
                                                      const float* __restrict__ rw) {
    int t = blockIdx.x, tid = threadIdx.x, lane = tid & 31, warp = tid >> 5;
    const float* xr = x + (size_t)t * Hdim;
    __shared__ float sred[8];
    __shared__ float slog[8][9];
    __shared__ float s_rms;

    float ss = 0.0f;
    for (int i = tid; i < Hdim; i += 256) { float v = xr[i]; ss += v * v; }
    ss = warpsum(ss);
    if (lane == 0) sred[warp] = ss;
    __syncthreads();
    if (tid == 0) {
        float tot = 0.0f;
        for (int w = 0; w < 8; w++) tot += sred[w];
        s_rms = rsqrtf(tot / (float)Hdim + 1e-6f);
    }
    __syncthreads();
    float rms = s_rms;

    float acc[8];
#pragma unroll
    for (int e = 0; e < 8; e++) acc[e] = 0.0f;
    for (int i = tid; i < Hdim; i += 256) {
        float tv = xr[i] * rms * nw[i];
        d_tn[(size_t)t * Hdim + i] = __float2half_rn(tv);
#pragma unroll
        for (int e = 0; e < 8; e++) acc[e] += tv * rw[i * Edim + e];
    }
#pragma unroll
    for (int e = 0; e < 8; e++) {
        float v = warpsum(acc[e]);
        if (lane == 0) slog[warp][e] = v;
    }
    __syncthreads();
    if (tid == 0) {
        float lg[8];
        for (int e = 0; e < 8; e++) {
            float s = 0.0f;
            for (int w = 0; w < 8; w++) s += slog[w][e];
            lg[e] = s;
        }
        float mx = lg[0];
        for (int e = 1; e < 8; e++) mx = fmaxf(mx, lg[e]);
        float af[8], sum = 0.0f;
        for (int e = 0; e < 8; e++) { af[e] = expf(lg[e] - mx); sum += af[e]; }
        float inv = 1.0f / sum;
        for (int e = 0; e < 8; e++) af[e] *= inv;
        int i1 = 0;
        for (int e = 1; e < 8; e++) if (af[e] > af[i1]) i1 = e;
        int i2 = (i1 == 0) ? 1 : 0;
        for (int e = 0; e < 8; e++) if (e != i1 && af[e] > af[i2]) i2 = e;
        float v1 = af[i1], v2 = af[i2], s2 = v1 + v2;
        d_topi[2 * t] = i1;  d_topi[2 * t + 1] = i2;
        d_topw[2 * t] = v1 / s2;  d_topw[2 * t + 1] = v2 / s2;
        atomicAdd(&d_counts[i1], 1);
        atomicAdd(&d_counts[i2], 1);
    }
}

__global__ void scan_kernel() {
    if (threadIdx.x == 0) {
        int o = 0;
        for (int e = 0; e < Edim; e++) { d_offsets[e] = o; o += d_counts[e]; }
        d_offsets[Edim] = o;
    }
}

__global__ void assign_kernel() {
    int t = blockIdx.x * blockDim.x + threadIdx.x;
    if (t >= Tdim) return;
    for (int k = 0; k < 2; k++) {
        int e = d_topi[2 * t + k];
        int p = d_offsets[e] + atomicAdd(&d_cursor[e], 1);
        d_rows[p] = t;
        d_wgt[p] = d_topw[2 * t + k];
    }
}

// ---------------- grouped GEMM, fp16 m16n8k16, CTA 256x128, warp 64x64 ----------------
// 8 warps as 4m x 2n; acc = 128 fp32 regs/thread; 1 CTA/SM.
// A in SMEM: fp16, 256 rows x 64B, granule-swizzled, read via ldmatrix.x4.
// B in SMEM: fp32 [k][n], pitch 528B, packed to fp16 in registers.
// MODE 0: gate (A = gathered d_tn -> d_g fp32).
// MODE 1: up   (A = gathered d_tn; epilogue reads d_g, silu, -> d_h fp16).
// MODE 2: down (A = d_h rows; atomic weighted scatter -> out).

#define BPH   528
#define ASTG  16384
#define STG   (ASTG + 32 * BPH)       // 33280
#define NSTG  4
#define SMEM_TOT (NSTG * STG + 2048)  // 135168

template <int MODE>
__global__ __launch_bounds__(256, 1) void mma_gemm(const float* __restrict__ W,
                                                   float* __restrict__ Out) {
    constexpr int NDIM = (MODE == 2) ? Hdim : Idim;
    constexpr int KDIM = (MODE == 2) ? Idim : Hdim;
    constexpr int NK = KDIM / 32;

    const int e = blockIdx.z;
    const int cnt = d_counts[e];
    const int m0 = blockIdx.x * 256;
    if (m0 >= cnt) return;
    const int base = d_offsets[e];
    const int n0 = blockIdx.y * 128;
    const int valid = cnt - m0;

    extern __shared__ char smem[];
    const uint32_t sb = smem_u32(smem);
    const int tid = threadIdx.x, wid = tid >> 5, lane = tid & 31;
    const int wm = wid & 3, wn = wid >> 2;
    const int qid = lane >> 2, kl = lane & 3;

    int*   tokS = (int*)(smem + NSTG * STG);
    float* wgtS = (float*)(smem + NSTG * STG + 1024);
    {
        int slot = base + m0 + min(tid, valid - 1);
        tokS[tid] = d_rows[slot];
        wgtS[tid] = d_wgt[slot];
    }
    __syncthreads();

    // ---- A staging: each thread copies 4 granules (rows r0+{0,64,128,192}) ----
    const int r0 = tid >> 2, gA = tid & 3;
    const __half* arow[4];
#pragma unroll
    for (int j = 0; j < 4; j++) {
        int rc = min(r0 + j * 64, valid - 1);
        if (MODE < 2) arow[j] = d_tn + (size_t)tokS[rc] * KDIM + gA * 8;
        else          arow[j] = d_h + (size_t)(base + m0 + rc) * KDIM + gA * 8;
    }
    const uint32_t sw = (gA ^ ((r0 >> 1) & 3)) * 16;   // identical for all 4 rows
    const float* Wsrc = W + (size_t)e * KDIM * NDIM + n0 + lane * 4;

    auto load_stage = [&](int kc, int buf) {
        uint32_t ab = sb + buf * STG;
        const int k0 = kc * 32;
#pragma unroll
        for (int j = 0; j < 4; j++)
            cp16(ab + (r0 + j * 64) * 64 + sw, arow[j] + k0);
        uint32_t bb = ab + ASTG;
#pragma unroll
        for (int j = 0; j < 4; j++) {
            int kk = j * 8 + wid;
            cp16(bb + kk * BPH + lane * 16, Wsrc + (size_t)(k0 + kk) * NDIM);
        }
        asm volatile("cp.async.commit_group;" ::: "memory");
    };

    // ---- ldmatrix per-lane address pieces ----
    const int t8 = lane >> 3;
    const int gt = t8 >> 1;                        // k-granule within ks16
    const int rL = (t8 & 1) * 8 + (lane & 7);      // row within 16-row frag
    uint32_t r64[4], swm[4];
#pragma unroll
    for (int mf = 0; mf < 4; mf++) {
        int r = wm * 64 + mf * 16 + rL;
        r64[mf] = r * 64;
        swm[mf] = (r >> 1) & 3;
    }

    float acc[4][8][4];
#pragma unroll
    for (int mf = 0; mf < 4; mf++)
#pragma unroll
        for (int nf = 0; nf < 8; nf++)
#pragma unroll
            for (int q = 0; q < 4; q++) acc[mf][nf][q] = 0.0f;

    load_stage(0, 0);
    load_stage(1, 1);
    load_stage(2, 2);

#pragma unroll 1
    for (int kc = 0; kc < NK; kc++) {
        if (kc < NK - 2)       asm volatile("cp.async.wait_group 2;" ::: "memory");
        else if (kc == NK - 2) asm volatile("cp.async.wait_group 1;" ::: "memory");
        else                   asm volatile("cp.async.wait_group 0;" ::: "memory");
        __syncthreads();
        if (kc + 3 < NK) load_stage(kc + 3, (kc + 3) & 3);

        const uint32_t Abase = sb + (kc & 3) * STG;
        const char* Bb = smem + (kc & 3) * STG + ASTG;
#pragma unroll
        for (int ks16 = 0; ks16 < 2; ks16++) {
            unsigned a[4][4];
#pragma unroll
            for (int mf = 0; mf < 4; mf++)
                ldsm4(a[mf], Abase + r64[mf] + (((ks16 * 2 + gt) ^ swm[mf]) << 4));
            const int ksr = ks16 * 16;
#pragma unroll
            for (int nf = 0; nf < 8; nf++) {
                const char* p = Bb + (wn * 64 + nf * 8 + qid) * 4;
                float b00 = *(const float*)(p + (ksr + 2 * kl) * BPH);
                float b01 = *(const float*)(p + (ksr + 2 * kl + 1) * BPH);
                float b10 = *(const float*)(p + (ksr + 2 * kl + 8) * BPH);
                float b11 = *(const float*)(p + (ksr + 2 * kl + 9) * BPH);
                unsigned b0 = pack2h(b00, b01);
                unsigned b1 = pack2h(b10, b11);
#pragma unroll
                for (int mf = 0; mf < 4; mf++)
                    mma_f16(acc[mf][nf], a[mf], b0, b1);
            }
        }
    }

    // ---------------- epilogue ----------------
#pragma unroll
    for (int mf = 0; mf < 4; mf++) {
#pragma unroll
        for (int half = 0; half < 2; half++) {
            int r = wm * 64 + mf * 16 + qid + half * 8;
            if (r >= valid) continue;
#pragma unroll
            for (int nf = 0; nf < 8; nf++) {
                int col = n0 + wn * 64 + nf * 8 + kl * 2;
                float v0 = acc[mf][nf][half * 2 + 0];
                float v1 = acc[mf][nf][half * 2 + 1];
                if (MODE == 0) {
                    *(float2*)(d_g + (size_t)(base + m0 + r) * Idim + col) =
                        make_float2(v0, v1);
                } else if (MODE == 1) {
                    size_t o = (size_t)(base + m0 + r) * Idim + col;
                    float2 g = *(const float2*)(d_g + o);
                    float h0 = g.x / (1.0f + expf(-g.x)) * v0;
                    float h1 = g.y / (1.0f + expf(-g.y)) * v1;
                    __half2 hv = __floats2half2_rn(h0, h1);
                    *(__half2*)(d_h + o) = hv;
                } else {
                    int tok = tokS[r];
                    float w = wgtS[r];
                    float* dst = Out + (size_t)tok * Hdim + col;
                    atomicAdd(dst + 0, w * v0);
                    atomicAdd(dst + 1, w * v1);
                }
            }
        }
    }
}

// ---------------- launch ----------------
extern "C" void kernel_launch(void* const* d_in, const int* in_sizes, int n_in,
                              void* d_out, int out_size) {
    const float* x  = (const float*)d_in[0];
    const float* nw = (const float*)d_in[1];
    const float* rw = (const float*)d_in[2];
    const float* wg = (const float*)d_in[3];
    const float* wu = (const float*)d_in[4];
    const float* wd = (const float*)d_in[5];
    float* out = (float*)d_out;

    static bool attr_done = false;
    if (!attr_done) {
        cudaFuncSetAttribute(mma_gemm<0>, cudaFuncAttributeMaxDynamicSharedMemorySize, SMEM_TOT);
        cudaFuncSetAttribute(mma_gemm<1>, cudaFuncAttributeMaxDynamicSharedMemorySize, SMEM_TOT);
        cudaFuncSetAttribute(mma_gemm<2>, cudaFuncAttributeMaxDynamicSharedMemorySize, SMEM_TOT);
        attr_done = true;
    }

    init_kernel<<<512, 256>>>(out);
    routing_kernel<<<Tdim, 256>>>(x, nw, rw);
    scan_kernel<<<1, 32>>>();
    assign_kernel<<<Tdim / 256, 256>>>();

    dim3 g1(TK / 256, Idim / 128, Edim);   // 16 x 32 x 8, most x exit early
    mma_gemm<0><<<g1, 256, SMEM_TOT>>>(wg, nullptr);   // gate -> d_g
    mma_gemm<1><<<g1, 256, SMEM_TOT>>>(wu, nullptr);   // up + silu -> d_h

    dim3 g2(TK / 256, Hdim / 128, Edim);   // 16 x 16 x 8
    mma_gemm<2><<<g2, 256, SMEM_TOT>>>(wd, out);       // down -> out (atomic)
}

// round 9
// speedup vs baseline: 1.0048x; 1.0048x over previous
#include <cuda_runtime.h>
#include <cuda_fp16.h>
#include <math.h>
#include <stdint.h>

#define Hdim 2048
#define Idim 4096
#define Edim 8
#define Tdim 2048
#define TK   4096   // T * K slots (always exact: every token picks 2 experts)

// ---------------- scratch (static device arrays; no allocations) ----------------
__device__ __half d_tn[(size_t)Tdim * Hdim];    // normalized tokens (fp16)
__device__ float  d_g[(size_t)TK * Idim];       // gate proj (fp32)
__device__ __half d_h[(size_t)TK * Idim];       // silu(g)*u (fp16)
__device__ __half d_wg16[(size_t)Edim * Hdim * Idim];  // fp16 weights
__device__ __half d_wu16[(size_t)Edim * Hdim * Idim];
__device__ __half d_wd16[(size_t)Edim * Idim * Hdim];
__device__ int    d_rows[TK];
__device__ float  d_wgt[TK];
__device__ int    d_topi[Tdim * 2];
__device__ float  d_topw[Tdim * 2];
__device__ int    d_counts[Edim];
__device__ int    d_cursor[Edim];
__device__ int    d_offsets[Edim + 1];

// ---------------- helpers ----------------
__device__ __forceinline__ float warpsum(float v) {
#pragma unroll
    for (int o = 16; o > 0; o >>= 1) v += __shfl_down_sync(0xFFFFFFFFu, v, o);
    return v;
}
__device__ __forceinline__ uint32_t smem_u32(const void* p) {
    uint32_t a;
    asm("{ .reg .u64 t; cvta.to.shared.u64 t, %1; cvt.u32.u64 %0, t; }" : "=r"(a) : "l"(p));
    return a;
}
__device__ __forceinline__ void cp16(uint32_t dst, const void* src) {
    asm volatile("cp.async.cg.shared.global [%0], [%1], 16;" :: "r"(dst), "l"(src) : "memory");
}
__device__ __forceinline__ void mma_f16(float c[4], const unsigned a[4],
                                        unsigned b0, unsigned b1) {
    asm volatile(
        "mma.sync.aligned.m16n8k16.row.col.f32.f16.f16.f32 "
        "{%0,%1,%2,%3}, {%4,%5,%6,%7}, {%8,%9}, {%0,%1,%2,%3};"
        : "+f"(c[0]), "+f"(c[1]), "+f"(c[2]), "+f"(c[3])
        : "r"(a[0]), "r"(a[1]), "r"(a[2]), "r"(a[3]), "r"(b0), "r"(b1));
}
__device__ __forceinline__ void ldsm4(unsigned r[4], uint32_t addr) {
    asm volatile("ldmatrix.sync.aligned.m8n8.x4.shared.b16 {%0,%1,%2,%3}, [%4];"
                 : "=r"(r[0]), "=r"(r[1]), "=r"(r[2]), "=r"(r[3]) : "r"(addr));
}
__device__ __forceinline__ void ldsm4t(unsigned r[4], uint32_t addr) {
    asm volatile("ldmatrix.sync.aligned.m8n8.x4.trans.shared.b16 {%0,%1,%2,%3}, [%4];"
                 : "=r"(r[0]), "=r"(r[1]), "=r"(r[2]), "=r"(r[3]) : "r"(addr));
}

// ---------------- weight fp32 -> fp16 conversion ----------------
__global__ __launch_bounds__(256) void conv_kernel(const float4* __restrict__ in,
                                                   uint2* __restrict__ out, int n4) {
    for (int i = blockIdx.x * blockDim.x + threadIdx.x; i < n4;
         i += gridDim.x * blockDim.x) {
        float4 v = in[i];
        __half2 lo = __floats2half2_rn(v.x, v.y);
        __half2 hi = __floats2half2_rn(v.z, v.w);
        out[i] = make_uint2(*(unsigned*)&lo, *(unsigned*)&hi);
    }
}

// ---------------- init ----------------
__global__ void init_kernel(float* __restrict__ out) {
    size_t n = (size_t)Tdim * Hdim;
    for (size_t i = (size_t)blockIdx.x * blockDim.x + threadIdx.x; i < n;
         i += (size_t)gridDim.x * blockDim.x)
        out[i] = 0.0f;
    if (blockIdx.x == 0 && threadIdx.x < Edim) {
        d_counts[threadIdx.x] = 0;
        d_cursor[threadIdx.x] = 0;
    }
}

// ---------------- RMSNorm + router + top-2 ----------------
__global__ __launch_bounds__(256) void routing_kernel(const float* __restrict__ x,
                                                      const float* __restrict__ nw,
                                                      const float* __restrict__ rw) {
    int t = blockIdx.x, tid = threadIdx.x, lane = tid & 31, warp = tid >> 5;
    const float* xr = x + (size_t)t * Hdim;
    __shared__ float sred[8];
    __shared__ float slog[8][9];
    __shared__ float s_rms;

    float ss = 0.0f;
    for (int i = tid; i < Hdim; i += 256) { float v = xr[i]; ss += v * v; }
    ss = warpsum(ss);
    if (lane == 0) sred[warp] = ss;
    __syncthreads();
    if (tid == 0) {
        float tot = 0.0f;
        for (int w = 0; w < 8; w++) tot += sred[w];
        s_rms = rsqrtf(tot / (float)Hdim + 1e-6f);
    }
    __syncthreads();
    float rms = s_rms;

    float acc[8];
#pragma unroll
    for (int e = 0; e < 8; e++) acc[e] = 0.0f;
    for (int i = tid; i < Hdim; i += 256) {
        float tv = xr[i] * rms * nw[i];
        d_tn[(size_t)t * Hdim + i] = __float2half_rn(tv);
#pragma unroll
        for (int e = 0; e < 8; e++) acc[e] += tv * rw[i * Edim + e];
    }
#pragma unroll
    for (int e = 0; e < 8; e++) {
        float v = warpsum(acc[e]);
        if (lane == 0) slog[warp][e] = v;
    }
    __syncthreads();
    if (tid == 0) {
        float lg[8];
        for (int e = 0; e < 8; e++) {
            float s = 0.0f;
            for (int w = 0; w < 8; w++) s += slog[w][e];
            lg[e] = s;
        }
        float mx = lg[0];
        for (int e = 1; e < 8; e++) mx = fmaxf(mx, lg[e]);
        float af[8], sum = 0.0f;
        for (int e = 0; e < 8; e++) { af[e] = expf(lg[e] - mx); sum += af[e]; }
        float inv = 1.0f / sum;
        for (int e = 0; e < 8; e++) af[e] *= inv;
        int i1 = 0;
        for (int e = 1; e < 8; e++) if (af[e] > af[i1]) i1 = e;
        int i2 = (i1 == 0) ? 1 : 0;
        for (int e = 0; e < 8; e++) if (e != i1 && af[e] > af[i2]) i2 = e;
        float v1 = af[i1], v2 = af[i2], s2 = v1 + v2;
        d_topi[2 * t] = i1;  d_topi[2 * t + 1] = i2;
        d_topw[2 * t] = v1 / s2;  d_topw[2 * t + 1] = v2 / s2;
        atomicAdd(&d_counts[i1], 1);
        atomicAdd(&d_counts[i2], 1);
    }
}

__global__ void scan_kernel() {
    if (threadIdx.x == 0) {
        int o = 0;
        for (int e = 0; e < Edim; e++) { d_offsets[e] = o; o += d_counts[e]; }
        d_offsets[Edim] = o;
    }
}

__global__ void assign_kernel() {
    int t = blockIdx.x * blockDim.x + threadIdx.x;
    if (t >= Tdim) return;
    for (int k = 0; k < 2; k++) {
        int e = d_topi[2 * t + k];
        int p = d_offsets[e] + atomicAdd(&d_cursor[e], 1);
        d_rows[p] = t;
        d_wgt[p] = d_topw[2 * t + k];
    }
}

// ---------------- grouped GEMM, fp16 both operands, 4-stage cp.async, 2 CTA/SM ----------------
// CTA tile 128x128, BK=32, 8 warps (2m x 4n), warp tile 64x32.
// A: fp16, 128 rows x 64B, granule-swizzled (g ^= (r>>1)&3), read via ldmatrix.x4.
// B: fp16, 32 k-rows x 256B, granule-swizzled (g ^= k&7), read via ldmatrix.x4.trans.
// MODE 0: gate (gathered d_tn x wg16 -> d_g fp32).
// MODE 1: up   (gathered d_tn x wu16; epilogue silu(d_g)*acc -> d_h fp16).
// MODE 2: down (d_h rows x wd16; atomic weighted scatter -> out).

#define ASTG  8192
#define STG   16384
#define NSTG  4
#define SMEM_TOT (NSTG * STG + 1024)   // 66560 -> 2 CTAs/SM

template <int MODE>
__global__ __launch_bounds__(256, 2) void mma_gemm(const __half* __restrict__ W,
                                                   float* __restrict__ Out) {
    constexpr int NDIM = (MODE == 2) ? Hdim : Idim;
    constexpr int KDIM = (MODE == 2) ? Idim : Hdim;
    constexpr int NK = KDIM / 32;

    const int e = blockIdx.z;
    const int cnt = d_counts[e];
    const int m0 = blockIdx.x * 128;
    if (m0 >= cnt) return;
    const int base = d_offsets[e];
    const int n0 = blockIdx.y * 128;
    const int valid = cnt - m0;

    extern __shared__ char smem[];
    const uint32_t sb = smem_u32(smem);
    const int tid = threadIdx.x, wid = tid >> 5, lane = tid & 31;
    const int wm = wid & 1, wn = wid >> 1;
    const int qid = lane >> 2, kl = lane & 3;

    int*   tokS = (int*)(smem + NSTG * STG);
    float* wgtS = (float*)(smem + NSTG * STG + 512);
    if (tid < 128) {
        int slot = base + m0 + min(tid, valid - 1);
        tokS[tid] = d_rows[slot];
        wgtS[tid] = d_wgt[slot];
    }
    __syncthreads();

    // ---- A staging: each thread copies 2 granules (rows r0, r0+64; k-group gA) ----
    const int r0 = tid >> 2, gA = tid & 3;
    const __half* arow0;
    const __half* arow1;
    if (MODE < 2) {
        arow0 = d_tn + (size_t)tokS[min(r0, valid - 1)] * KDIM + gA * 8;
        arow1 = d_tn + (size_t)tokS[min(r0 + 64, valid - 1)] * KDIM + gA * 8;
    } else {
        arow0 = d_h + (size_t)(base + m0 + min(r0, valid - 1)) * KDIM + gA * 8;
        arow1 = d_h + (size_t)(base + m0 + min(r0 + 64, valid - 1)) * KDIM + gA * 8;
    }
    const uint32_t swA = (gA ^ ((r0 >> 1) & 3)) * 16;
    const uint32_t adst0 = r0 * 64 + swA;
    const uint32_t adst1 = (r0 + 64) * 64 + swA;

    // ---- B staging: 32 k-rows x 256B; thread -> row kk, granules gB, gB+8 ----
    const int kk = tid >> 3, gB = tid & 7;
    const __half* brow = W + (size_t)e * KDIM * NDIM + (size_t)kk * NDIM + n0;
    const uint32_t bdst0 = kk * 256 + ((gB)     ^ (kk & 7)) * 16;
    const uint32_t bdst1 = kk * 256 + ((gB + 8) ^ (kk & 7)) * 16;

    auto load_stage = [&](int kc, int buf) {
        uint32_t ab = sb + buf * STG;
        const int k0 = kc * 32;
        cp16(ab + adst0, arow0 + k0);
        cp16(ab + adst1, arow1 + k0);
        uint32_t bb = ab + ASTG;
        const __half* bs = brow + (size_t)k0 * NDIM;
        cp16(bb + bdst0, bs + gB * 8);
        cp16(bb + bdst1, bs + gB * 8 + 64);
        asm volatile("cp.async.commit_group;" ::: "memory");
    };

    // ---- ldmatrix per-lane address pieces ----
    const int t8 = lane >> 3;
    const int gt = t8 >> 1;                        // A: k-granule within ks16
    const int rL = (t8 & 1) * 8 + (lane & 7);      // A: row within 16-row frag
    uint32_t r64[4], swm[4];
#pragma unroll
    for (int mf = 0; mf < 4; mf++) {
        int r = wm * 64 + mf * 16 + rL;
        r64[mf] = r * 64;
        swm[mf] = (r >> 1) & 3;
    }
    // B: lane -> k-row (lane&15), n-octet (lane>>4)
    const int bk = lane & 15, bo = lane >> 4;
    const uint32_t brow16 = (uint32_t)bk * 256;
    const int bswk = bk & 7;

    float acc[4][4][4];
#pragma unroll
    for (int mf = 0; mf < 4; mf++)
#pragma unroll
        for (int nf = 0; nf < 4; nf++)
#pragma unroll
            for (int q = 0; q < 4; q++) acc[mf][nf][q] = 0.0f;

    load_stage(0, 0);
    load_stage(1, 1);
    load_stage(2, 2);

#pragma unroll 1
    for (int kc = 0; kc < NK; kc++) {
        if (kc < NK - 2)       asm volatile("cp.async.wait_group 2;" ::: "memory");
        else if (kc == NK - 2) asm volatile("cp.async.wait_group 1;" ::: "memory");
        else                   asm volatile("cp.async.wait_group 0;" ::: "memory");
        __syncthreads();
        if (kc + 3 < NK) load_stage(kc + 3, (kc + 3) & 3);

        const uint32_t Abase = sb + (kc & 3) * STG;
        const uint32_t Bbase = Abase + ASTG;
#pragma unroll
        for (int ks16 = 0; ks16 < 2; ks16++) {
            unsigned a[4][4];
#pragma unroll
            for (int mf = 0; mf < 4; mf++)
                ldsm4(a[mf], Abase + r64[mf] + (((ks16 * 2 + gt) ^ swm[mf]) << 4));
            unsigned br[2][4];
#pragma unroll
            for (int j = 0; j < 2; j++) {
                uint32_t addr = Bbase + (ks16 * 16 + bk) * 256 +
                                (uint32_t)(((wn * 4 + j * 2 + bo) ^ bswk) << 4);
                ldsm4t(br[j], addr);
            }
#pragma unroll
            for (int nf = 0; nf < 4; nf++) {
                unsigned b0 = br[nf >> 1][(nf & 1) * 2 + 0];
                unsigned b1 = br[nf >> 1][(nf & 1) * 2 + 1];
#pragma unroll
                for (int mf = 0; mf < 4; mf++)
                    mma_f16(acc[mf][nf], a[mf], b0, b1);
            }
        }
    }

    // ---------------- epilogue ----------------
#pragma unroll
    for (int mf = 0; mf < 4; mf++) {
#pragma unroll
        for (int half = 0; half < 2; half++) {
            int r = wm * 64 + mf * 16 + qid + half * 8;
            if (r >= valid) continue;
#pragma unroll
            for (int nf = 0; nf < 4; nf++) {
                int col = n0 + wn * 32 + nf * 8 + kl * 2;
                float v0 = acc[mf][nf][half * 2 + 0];
                float v1 = acc[mf][nf][half * 2 + 1];
                if (MODE == 0) {
                    *(float2*)(d_g + (size_t)(base + m0 + r) * Idim + col) =
                        make_float2(v0, v1);
                } else if (MODE == 1) {
                    size_t o = (size_t)(base + m0 + r) * Idim + col;
                    float2 g = *(const float2*)(d_g + o);
                    float h0 = g.x / (1.0f + expf(-g.x)) * v0;
                    float h1 = g.y / (1.0f + expf(-g.y)) * v1;
                    *(__half2*)(d_h + o) = __floats2half2_rn(h0, h1);
                } else {
                    int tok = tokS[r];
                    float w = wgtS[r];
                    float* dst = Out + (size_t)tok * Hdim + col;
                    atomicAdd(dst + 0, w * v0);
                    atomicAdd(dst + 1, w * v1);
                }
            }
        }
    }
}

// ---------------- launch ----------------
extern "C" void kernel_launch(void* const* d_in, const int* in_sizes, int n_in,
                              void* d_out, int out_size) {
    const float* x  = (const float*)d_in[0];
    const float* nw = (const float*)d_in[1];
    const float* rw = (const float*)d_in[2];
    const float* wg = (const float*)d_in[3];
    const float* wu = (const float*)d_in[4];
    const float* wd = (const float*)d_in[5];
    float* out = (float*)d_out;

    static bool attr_done = false;
    if (!attr_done) {
        cudaFuncSetAttribute(mma_gemm<0>, cudaFuncAttributeMaxDynamicSharedMemorySize, SMEM_TOT);
        cudaFuncSetAttribute(mma_gemm<1>, cudaFuncAttributeMaxDynamicSharedMemorySize, SMEM_TOT);
        cudaFuncSetAttribute(mma_gemm<2>, cudaFuncAttributeMaxDynamicSharedMemorySize, SMEM_TOT);
        attr_done = true;
    }

    // weight fp32 -> fp16 (static __device__ targets; resolve addresses host-side)
    static void* wg16_p = nullptr;
    static void* wu16_p = nullptr;
    static void* wd16_p = nullptr;
    if (!wg16_p) {
        cudaGetSymbolAddress(&wg16_p, d_wg16);
        cudaGetSymbolAddress(&wu16_p, d_wu16);
        cudaGetSymbolAddress(&wd16_p, d_wd16);
    }
    const int n4 = Edim * Hdim * Idim / 4;   // 16,777,216
    conv_kernel<<<2048, 256>>>((const float4*)wg, (uint2*)wg16_p, n4);
    conv_kernel<<<2048, 256>>>((const float4*)wu, (uint2*)wu16_p, n4);
    conv_kernel<<<2048, 256>>>((const float4*)wd, (uint2*)wd16_p, n4);

    init_kernel<<<512, 256>>>(out);
    routing_kernel<<<Tdim, 256>>>(x, nw, rw);
    scan_kernel<<<1, 32>>>();
    assign_kernel<<<Tdim / 256, 256>>>();

    dim3 g1(TK / 128, Idim / 128, Edim);   // 32 x 32 x 8, most x exit early
    mma_gemm<0><<<g1, 256, SMEM_TOT>>>((const __half*)wg16_p, nullptr);  // gate
    mma_gemm<1><<<g1, 256, SMEM_TOT>>>((const __half*)wu16_p, nullptr);  // up + silu

    dim3 g2(TK / 128, Hdim / 128, Edim);   // 32 x 16 x 8
    mma_gemm<2><<<g2, 256, SMEM_TOT>>>((const __half*)wd16_p, out);      // down
}

// round 10
// speedup vs baseline: 1.1976x; 1.1918x over previous
#include <cuda_runtime.h>
#include <cuda_fp16.h>
#include <math.h>
#include <stdint.h>

#define Hdim 2048
#define Idim 4096
#define Edim 8
#define Tdim 2048
#define TK   4096   // T * K slots (always exact: every token picks 2 experts)

// ---------------- scratch (static device arrays; no allocations) ----------------
__device__ __half d_tn[(size_t)Tdim * Hdim];  // normalized tokens (fp16)
__device__ float  d_g[(size_t)TK * Idim];     // gate proj (fp32)
__device__ float  d_u[(size_t)TK * Idim];     // up proj (fp32)
__device__ __half d_h[(size_t)TK * Idim];     // silu(g)*u (fp16)
__device__ int    d_rows[TK];
__device__ float  d_wgt[TK];
__device__ int    d_topi[Tdim * 2];
__device__ float  d_topw[Tdim * 2];
__device__ int    d_counts[Edim];
__device__ int    d_cursor[Edim];
__device__ int    d_offsets[Edim + 1];

// ---------------- helpers ----------------
__device__ __forceinline__ float warpsum(float v) {
#pragma unroll
    for (int o = 16; o > 0; o >>= 1) v += __shfl_down_sync(0xFFFFFFFFu, v, o);
    return v;
}
__device__ __forceinline__ uint32_t smem_u32(const void* p) {
    uint32_t a;
    asm("{ .reg .u64 t; cvta.to.shared.u64 t, %1; cvt.u32.u64 %0, t; }" : "=r"(a) : "l"(p));
    return a;
}
__device__ __forceinline__ void cp16(uint32_t dst, const void* src) {
    asm volatile("cp.async.cg.shared.global [%0], [%1], 16;" :: "r"(dst), "l"(src) : "memory");
}
__device__ __forceinline__ unsigned pack2h(float lo, float hi) {
    __half2 h = __floats2half2_rn(lo, hi);   // .x (lo) in low 16 bits
    return *reinterpret_cast<unsigned*>(&h);
}
// fp16-accumulate MMA: D,C are f16x2 pairs
__device__ __forceinline__ void mma_f16acc(unsigned& d0, unsigned& d1,
                                           const unsigned a[4], unsigned b0, unsigned b1,
                                           unsigned c0, unsigned c1) {
    asm volatile(
        "mma.sync.aligned.m16n8k16.row.col.f16.f16.f16.f16 "
        "{%0,%1}, {%2,%3,%4,%5}, {%6,%7}, {%8,%9};"
        : "=r"(d0), "=r"(d1)
        : "r"(a[0]), "r"(a[1]), "r"(a[2]), "r"(a[3]), "r"(b0), "r"(b1),
          "r"(c0), "r"(c1));
}
__device__ __forceinline__ void ldsm4(unsigned r[4], uint32_t addr) {
    asm volatile("ldmatrix.sync.aligned.m8n8.x4.shared.b16 {%0,%1,%2,%3}, [%4];"
                 : "=r"(r[0]), "=r"(r[1]), "=r"(r[2]), "=r"(r[3]) : "r"(addr));
}

// ---------------- init ----------------
__global__ void init_kernel(float* __restrict__ out) {
    size_t n = (size_t)Tdim * Hdim;
    for (size_t i = (size_t)blockIdx.x * blockDim.x + threadIdx.x; i < n;
         i += (size_t)gridDim.x * blockDim.x)
        out[i] = 0.0f;
    if (blockIdx.x == 0 && threadIdx.x < Edim) {
        d_counts[threadIdx.x] = 0;
        d_cursor[threadIdx.x] = 0;
    }
}

// ---------------- RMSNorm + router + top-2 ----------------
__global__ __launch_bounds__(256) void routing_kernel(const float* __restrict__ x,
                                                      const float* __restrict__ nw,
                                                      const float* __restrict__ rw) {
    int t = blockIdx.x, tid = threadIdx.x, lane = tid & 31, warp = tid >> 5;
    const float* xr = x + (size_t)t * Hdim;
    __shared__ float sred[8];
    __shared__ float slog[8][9];
    __shared__ float s_rms;

    float ss = 0.0f;
    for (int i = tid; i < Hdim; i += 256) { float v = xr[i]; ss += v * v; }
    ss = warpsum(ss);
    if (lane == 0) sred[warp] = ss;
    __syncthreads();
    if (tid == 0) {
        float tot = 0.0f;
        for (int w = 0; w < 8; w++) tot += sred[w];
        s_rms = rsqrtf(tot / (float)Hdim + 1e-6f);
    }
    __syncthreads();
    float rms = s_rms;

    float acc[8];
#pragma unroll
    for (int e = 0; e < 8; e++) acc[e] = 0.0f;
    for (int i = tid; i < Hdim; i += 256) {
        float tv = xr[i] * rms * nw[i];
        d_tn[(size_t)t * Hdim + i] = __float2half_rn(tv);
#pragma unroll
        for (int e = 0; e < 8; e++) acc[e] += tv * rw[i * Edim + e];
    }
#pragma unroll
    for (int e = 0; e < 8; e++) {
        float v = warpsum(acc[e]);
        if (lane == 0) slog[warp][e] = v;
    }
    __syncthreads();
    if (tid == 0) {
        float lg[8];
        for (int e = 0; e < 8; e++) {
            float s = 0.0f;
            for (int w = 0; w < 8; w++) s += slog[w][e];
            lg[e] = s;
        }
        float mx = lg[0];
        for (int e = 1; e < 8; e++) mx = fmaxf(mx, lg[e]);
        float af[8], sum = 0.0f;
        for (int e = 0; e < 8; e++) { af[e] = expf(lg[e] - mx); sum += af[e]; }
        float inv = 1.0f / sum;
        for (int e = 0; e < 8; e++) af[e] *= inv;
        int i1 = 0;
        for (int e = 1; e < 8; e++) if (af[e] > af[i1]) i1 = e;
        int i2 = (i1 == 0) ? 1 : 0;
        for (int e = 0; e < 8; e++) if (e != i1 && af[e] > af[i2]) i2 = e;
        float v1 = af[i1], v2 = af[i2], s2 = v1 + v2;
        d_topi[2 * t] = i1;  d_topi[2 * t + 1] = i2;
        d_topw[2 * t] = v1 / s2;  d_topw[2 * t + 1] = v2 / s2;
        atomicAdd(&d_counts[i1], 1);
        atomicAdd(&d_counts[i2], 1);
    }
}

__global__ void scan_kernel() {
    if (threadIdx.x == 0) {
        int o = 0;
        for (int e = 0; e < Edim; e++) { d_offsets[e] = o; o += d_counts[e]; }
        d_offsets[Edim] = o;
    }
}

__global__ void assign_kernel() {
    int t = blockIdx.x * blockDim.x + threadIdx.x;
    if (t >= Tdim) return;
    for (int k = 0; k < 2; k++) {
        int e = d_topi[2 * t + k];
        int p = d_offsets[e] + atomicAdd(&d_cursor[e], 1);
        d_rows[p] = t;
        d_wgt[p] = d_topw[2 * t + k];
    }
}

// ---------------- grouped GEMM, fp16-accum m16n8k16, 4-stage cp.async, 2 CTA/SM ----------------
// CTA tile 128x128, BK=32, 8 warps (2m x 4n), warp tile 64x32.
// A in SMEM: fp16, 128 rows x 64B, granule-swizzled (g ^= (r>>1)&3), read via ldmatrix.x4.
// B in SMEM: fp32 [k][n], pitch 528B, packed to fp16 in registers.
// Inner loop: per-fragment fp16 accumulator window over one BK=32 chunk (2 chained MMAs),
// unpacked and added to fp32 master accumulators each chunk.
// MODE 0: projection (A = gathered d_tn -> d_g/d_u per z&1). N=Idim, K=Hdim.
// MODE 1: down (A = d_h rows, atomic weighted scatter -> out). N=Hdim, K=Idim.

#define BPH   528
#define ASTG  8192
#define STG   (ASTG + 32 * BPH)       // 25088
#define NSTG  4
#define SMEM_TOT (NSTG * STG + 1024)  // 101376 -> 2 CTAs/SM

template <int MODE>
__global__ __launch_bounds__(256, 2) void mma_gemm(const float* __restrict__ W0,
                                                   const float* __restrict__ W1,
                                                   float* __restrict__ Out) {
    constexpr int NDIM = (MODE == 1) ? Hdim : Idim;
    constexpr int KDIM = (MODE == 1) ? Idim : Hdim;
    constexpr int NK = KDIM / 32;

    const int zz = blockIdx.z;
    const int e = (MODE == 0) ? (zz >> 1) : zz;
    const int cnt = d_counts[e];
    const int m0 = blockIdx.x * 128;
    if (m0 >= cnt) return;
    const int base = d_offsets[e];
    const int n0 = blockIdx.y * 128;
    const int valid = cnt - m0;

    const float* W = (MODE == 0) ? ((zz & 1) ? W1 : W0) : W0;
    float* Dst = (MODE == 0) ? (((zz & 1) ? d_u : d_g)) : Out;

    extern __shared__ char smem[];
    const uint32_t sb = smem_u32(smem);
    const int tid = threadIdx.x, wid = tid >> 5, lane = tid & 31;
    const int wm = wid & 1, wn = wid >> 1;
    const int qid = lane >> 2, kl = lane & 3;

    int*   tokS = (int*)(smem + NSTG * STG);
    float* wgtS = (float*)(smem + NSTG * STG + 512);
    if (tid < 128) {
        int slot = base + m0 + min(tid, valid - 1);
        tokS[tid] = d_rows[slot];
        wgtS[tid] = d_wgt[slot];
    }
    __syncthreads();

    // ---- A staging: each thread copies 2 granules (rows r0, r0+64; k-group g) ----
    const int r0 = tid >> 2, gA = tid & 3;
    const __half* arow0;
    const __half* arow1;
    if (MODE == 0) {
        arow0 = d_tn + (size_t)tokS[min(r0, valid - 1)] * KDIM + gA * 8;
        arow1 = d_tn + (size_t)tokS[min(r0 + 64, valid - 1)] * KDIM + gA * 8;
    } else {
        arow0 = d_h + (size_t)(base + m0 + min(r0, valid - 1)) * KDIM + gA * 8;
        arow1 = d_h + (size_t)(base + m0 + min(r0 + 64, valid - 1)) * KDIM + gA * 8;
    }
    const uint32_t sw = (gA ^ ((r0 >> 1) & 3)) * 16;   // same for r0 and r0+64
    const uint32_t adst0 = r0 * 64 + sw;
    const uint32_t adst1 = (r0 + 64) * 64 + sw;

    const float* Wsrc = W + (size_t)e * KDIM * NDIM + n0 + lane * 4;

    auto load_stage = [&](int kc, int buf) {
        uint32_t ab = sb + buf * STG;
        const int k0 = kc * 32;
        cp16(ab + adst0, arow0 + k0);
        cp16(ab + adst1, arow1 + k0);
        uint32_t bb = ab + ASTG;
#pragma unroll
        for (int j = 0; j < 4; j++) {
            int kk = j * 8 + wid;
            cp16(bb + kk * BPH + lane * 16, Wsrc + (size_t)(k0 + kk) * NDIM);
        }
        asm volatile("cp.async.commit_group;" ::: "memory");
    };

    // ---- ldmatrix per-lane address pieces ----
    const int t8 = lane >> 3;
    const int gt = t8 >> 1;                        // k-granule within ks16
    const int rL = (t8 & 1) * 8 + (lane & 7);      // row within 16-row frag
    uint32_t r64[4], swm[4];
#pragma unroll
    for (int mf = 0; mf < 4; mf++) {
        int r = wm * 64 + mf * 16 + rL;
        r64[mf] = r * 64;
        swm[mf] = (r >> 1) & 3;
    }

    float acc[4][4][4];
#pragma unroll
    for (int mf = 0; mf < 4; mf++)
#pragma unroll
        for (int nf = 0; nf < 4; nf++)
#pragma unroll
            for (int q = 0; q < 4; q++) acc[mf][nf][q] = 0.0f;

    load_stage(0, 0);
    load_stage(1, 1);
    load_stage(2, 2);

#pragma unroll 1
    for (int kc = 0; kc < NK; kc++) {
        if (kc < NK - 2)       asm volatile("cp.async.wait_group 2;" ::: "memory");
        else if (kc == NK - 2) asm volatile("cp.async.wait_group 1;" ::: "memory");
        else                   asm volatile("cp.async.wait_group 0;" ::: "memory");
        __syncthreads();
        if (kc + 3 < NK) load_stage(kc + 3, (kc + 3) & 3);

        const uint32_t Abase = sb + (kc & 3) * STG;
        const char* Bb = smem + (kc & 3) * STG + ASTG;

        // load A fragments for both k16 steps of this chunk
        unsigned a[2][4][4];
#pragma unroll
        for (int ks16 = 0; ks16 < 2; ks16++)
#pragma unroll
            for (int mf = 0; mf < 4; mf++)
                ldsm4(a[ks16][mf], Abase + r64[mf] + (((ks16 * 2 + gt) ^ swm[mf]) << 4));

#pragma unroll
        for (int nf = 0; nf < 4; nf++) {
            const char* p = Bb + (wn * 32 + nf * 8 + qid) * 4;
            unsigned bp[2][2];
#pragma unroll
            for (int ks16 = 0; ks16 < 2; ks16++) {
                const int ksr = ks16 * 16;
                float b00 = *(const float*)(p + (ksr + 2 * kl) * BPH);
                float b01 = *(const float*)(p + (ksr + 2 * kl + 1) * BPH);
                float b10 = *(const float*)(p + (ksr + 2 * kl + 8) * BPH);
                float b11 = *(const float*)(p + (ksr + 2 * kl + 9) * BPH);
                bp[ks16][0] = pack2h(b00, b01);
                bp[ks16][1] = pack2h(b10, b11);
            }
#pragma unroll
            for (int mf = 0; mf < 4; mf++) {
                unsigned w0, w1;
                mma_f16acc(w0, w1, a[0][mf], bp[0][0], bp[0][1], 0u, 0u);
                mma_f16acc(w0, w1, a[1][mf], bp[1][0], bp[1][1], w0, w1);
                float2 lo = __half22float2(*(const __half2*)&w0);
                float2 hi = __half22float2(*(const __half2*)&w1);
                acc[mf][nf][0] += lo.x;
                acc[mf][nf][1] += lo.y;
                acc[mf][nf][2] += hi.x;
                acc[mf][nf][3] += hi.y;
            }
        }
    }

    // ---------------- epilogue ----------------
#pragma unroll
    for (int mf = 0; mf < 4; mf++) {
#pragma unroll
        for (int half = 0; half < 2; half++) {
            int r = wm * 64 + mf * 16 + qid + half * 8;
            if (r >= valid) continue;
#pragma unroll
            for (int nf = 0; nf < 4; nf++) {
                int col = n0 + wn * 32 + nf * 8 + kl * 2;
                float v0 = acc[mf][nf][half * 2 + 0];
                float v1 = acc[mf][nf][half * 2 + 1];
                if (MODE == 0) {
                    *(float2*)(Dst + (size_t)(base + m0 + r) * Idim + col) =
                        make_float2(v0, v1);
                } else {
                    int tok = tokS[r];
                    float w = wgtS[r];
                    float* dst = Dst + (size_t)tok * Hdim + col;
                    atomicAdd(dst + 0, w * v0);
                    atomicAdd(dst + 1, w * v1);
                }
            }
        }
    }
}

// ---------------- h = silu(g) * u (fp16 for the down GEMM) ----------------
__global__ void silu_kernel() {
    size_t n = (size_t)TK * Idim;
    for (size_t i = (size_t)blockIdx.x * blockDim.x + threadIdx.x; i < n;
         i += (size_t)gridDim.x * blockDim.x) {
        float g = d_g[i], u = d_u[i];
        float h = g / (1.0f + expf(-g)) * u;
        d_h[i] = __float2half_rn(h);
    }
}

// ---------------- launch ----------------
extern "C" void kernel_launch(void* const* d_in, const int* in_sizes, int n_in,
                              void* d_out, int out_size) {
    const float* x  = (const float*)d_in[0];
    const float* nw = (const float*)d_in[1];
    const float* rw = (const float*)d_in[2];
    const float* wg = (const float*)d_in[3];
    const float* wu = (const float*)d_in[4];
    const float* wd = (const float*)d_in[5];
    float* out = (float*)d_out;

    static bool attr_done = false;
    if (!attr_done) {
        cudaFuncSetAttribute(mma_gemm<0>, cudaFuncAttributeMaxDynamicSharedMemorySize, SMEM_TOT);
        cudaFuncSetAttribute(mma_gemm<1>, cudaFuncAttributeMaxDynamicSharedMemorySize, SMEM_TOT);
        attr_done = true;
    }

    init_kernel<<<512, 256>>>(out);
    routing_kernel<<<Tdim, 256>>>(x, nw, rw);
    scan_kernel<<<1, 32>>>();
    assign_kernel<<<Tdim / 256, 256>>>();

    // gate+up in one launch: z = expert*2 + {0:gate, 1:up}
    dim3 g1(TK / 128, Idim / 128, Edim * 2);   // 32 x 32 x 16, most x exit early
    mma_gemm<0><<<g1, 256, SMEM_TOT>>>(wg, wu, nullptr);

    silu_kernel<<<2048, 256>>>();

    dim3 g2(TK / 128, Hdim / 128, Edim);       // 32 x 16 x 8
    mma_gemm<1><<<g2, 256, SMEM_TOT>>>(wd, nullptr, out);
}